// round 8
// baseline (speedup 1.0000x reference)
#include <cuda_runtime.h>

#define N_NODES 50000
#define N_EDGES 800000
#define D 128
#define NBATCH 64
#define EPW 32                 // edges per warp in k_edges (800000 = 25000*32)

// Device scratch (allocation-free). Zero-initialized at module load; every
// kernel_launch leaves them zeroed again (self-restoring), so no init kernel.
__device__ float g_agg[N_NODES * D];   // neighbor sums (zeroed by k_epilogue)
__device__ float g_S[NBATCH * D];      // per-batch pooled sums (zeroed by k_pool)
__device__ float g_cnt[NBATCH];        // per-batch node counts (zeroed by k_pool)

// ---------------------------------------------------------------------------
// 1) edge scatter: one warp per 32 edges.
//    Each lane loads one src and one dst (coalesced 128B index loads), then
//    32 independent gather(+L1-bypass) + vector-RED chains (high MLP).
// ---------------------------------------------------------------------------
__global__ void __launch_bounds__(256) k_edges(const float* __restrict__ x,
                                               const int* __restrict__ ei) {
    int warp = (blockIdx.x * blockDim.x + threadIdx.x) >> 5;
    int lane = threadIdx.x & 31;
    long long base = (long long)warp * EPW;
    if (base >= N_EDGES) return;

    int src = __ldg(&ei[base + lane]);             // 32 srcs, coalesced
    int dst = __ldg(&ei[N_EDGES + base + lane]);   // 32 dsts, coalesced

    const float4* x4 = reinterpret_cast<const float4*>(x);

    #pragma unroll
    for (int j = 0; j < EPW; j++) {
        int s = __shfl_sync(0xffffffffu, src, j);
        int d = __shfl_sync(0xffffffffu, dst, j);
        float4 v = __ldcg(&x4[(size_t)s * 32 + lane]);   // bypass L1 (hit ~0%)
        float* p = g_agg + (size_t)d * D + lane * 4;
        asm volatile("red.global.add.v4.f32 [%0], {%1, %2, %3, %4};"
                     :: "l"(p), "f"(v.x), "f"(v.y), "f"(v.z), "f"(v.w)
                     : "memory");
    }
}

// ---------------------------------------------------------------------------
// 2) epilogue: out = relu(scale*x + agg), re-zero agg, and per-batch pooled
//    row-sums with run-length compression (batch is sorted).
//    One warp per 16 consecutive rows; lane = one float4.
// ---------------------------------------------------------------------------
#define EPI_ROWS 16

__global__ void __launch_bounds__(256) k_epilogue(const float* __restrict__ x,
                                                  const float* __restrict__ eps,
                                                  const int* __restrict__ batch,
                                                  float* __restrict__ out) {
    int warp = (blockIdx.x * blockDim.x + threadIdx.x) >> 5;
    int lane = threadIdx.x & 31;
    int r0 = warp * EPI_ROWS;
    if (r0 >= N_NODES) return;
    int r1 = r0 + EPI_ROWS; if (r1 > N_NODES) r1 = N_NODES;

    float scale = 1.0f + eps[0];
    float4* agg4 = reinterpret_cast<float4*>(g_agg);
    const float4* x4 = reinterpret_cast<const float4*>(x);
    float4* out4 = reinterpret_cast<float4*>(out);
    const float4 zero4 = make_float4(0.f, 0.f, 0.f, 0.f);

    float4 acc = zero4;
    int cnt = 0;
    int cur = batch[r0];   // broadcast load

    for (int r = r0; r < r1; r++) {
        size_t idx = (size_t)r * 32 + lane;
        float4 a  = __ldcg(&agg4[idx]);    // read-once data: bypass L1
        float4 xv = x4[idx];
        float4 v;
        v.x = fmaxf(fmaf(xv.x, scale, a.x), 0.f);
        v.y = fmaxf(fmaf(xv.y, scale, a.y), 0.f);
        v.z = fmaxf(fmaf(xv.z, scale, a.z), 0.f);
        v.w = fmaxf(fmaf(xv.w, scale, a.w), 0.f);
        out4[idx] = v;
        agg4[idx] = zero4;                 // self-restore for next replay

        int b = batch[r];
        if (b != cur) {
            float* p = &g_S[cur * D + lane * 4];
            asm volatile("red.global.add.v4.f32 [%0], {%1, %2, %3, %4};"
                         :: "l"(p), "f"(acc.x), "f"(acc.y), "f"(acc.z), "f"(acc.w)
                         : "memory");
            if (lane == 0) atomicAdd(&g_cnt[cur], (float)cnt);
            cur = b; acc = zero4; cnt = 0;
        }
        acc.x += v.x; acc.y += v.y; acc.z += v.z; acc.w += v.w;
        cnt++;
    }
    {
        float* p = &g_S[cur * D + lane * 4];
        asm volatile("red.global.add.v4.f32 [%0], {%1, %2, %3, %4};"
                     :: "l"(p), "f"(acc.x), "f"(acc.y), "f"(acc.z), "f"(acc.w)
                     : "memory");
        if (lane == 0) atomicAdd(&g_cnt[cur], (float)cnt);
    }
}

// ---------------------------------------------------------------------------
// 3) pooled2[b] = S[b] @ W + cnt[b]*bias  (64x128x128). Reads then re-zeroes
//    g_S / g_cnt. 4 independent FMA chains, full unroll.
// ---------------------------------------------------------------------------
__global__ void k_pool(const float* __restrict__ W,
                       const float* __restrict__ bias,
                       float* __restrict__ out2) {
    int b = blockIdx.x;     // 0..63
    int j = threadIdx.x;    // 0..127
    __shared__ float s[D];
    __shared__ float cntf;
    s[j] = g_S[b * D + j];
    g_S[b * D + j] = 0.0f;                 // self-restore
    if (j == 0) { cntf = g_cnt[b]; g_cnt[b] = 0.0f; }
    __syncthreads();

    float a0 = 0.f, a1 = 0.f, a2 = 0.f, a3 = 0.f;
    #pragma unroll
    for (int k = 0; k < D; k += 4) {
        a0 = fmaf(s[k + 0], __ldg(&W[(k + 0) * D + j]), a0);
        a1 = fmaf(s[k + 1], __ldg(&W[(k + 1) * D + j]), a1);
        a2 = fmaf(s[k + 2], __ldg(&W[(k + 2) * D + j]), a2);
        a3 = fmaf(s[k + 3], __ldg(&W[(k + 3) * D + j]), a3);
    }
    out2[b * D + j] = cntf * bias[j] + ((a0 + a1) + (a2 + a3));
}

// ---------------------------------------------------------------------------
// launch: x, eps, W_pred, b_pred, edge_index, batch -> out | pooled2
// ---------------------------------------------------------------------------
extern "C" void kernel_launch(void* const* d_in, const int* in_sizes, int n_in,
                              void* d_out, int out_size) {
    const float* x     = (const float*)d_in[0];
    const float* eps   = (const float*)d_in[1];
    const float* Wp    = (const float*)d_in[2];
    const float* bp    = (const float*)d_in[3];
    const int*   ei    = (const int*)d_in[4];
    const int*   batch = (const int*)d_in[5];

    float* out  = (float*)d_out;
    float* out2 = out + (size_t)N_NODES * D;

    // edge scatter: one warp per EPW edges
    {
        int warps = (N_EDGES + EPW - 1) / EPW;               // 25000
        int blocks = (warps * 32 + 255) / 256;               // 3125
        k_edges<<<blocks, 256>>>(x, ei);
    }

    // epilogue: relu + out + agg re-zero + batch partial sums
    {
        int warps = (N_NODES + EPI_ROWS - 1) / EPI_ROWS;     // 3125
        int blocks = (warps * 32 + 255) / 256;               // 391
        k_epilogue<<<blocks, 256>>>(x, eps, batch, out);
    }

    // tiny pooled GEMM
    k_pool<<<NBATCH, 128>>>(Wp, bp, out2);
}